// round 13
// baseline (speedup 1.0000x reference)
#include <cuda_runtime.h>
#include <cstdint>

// Shape (from reference setup_inputs): B=64, S=1024, D=512, T=2048.
// S, D, T re-derived from in_sizes/out_size at launch; B fixed.
#define BATCH 64
#define MAX_S 1024
#define ROWS  8        // output rows per 128-lane group
#define NGRP  4        // groups per block (512 threads)
#define RPB   (ROWS * NGRP)   // 32 rows per block

// ---------------------------------------------------------------------------
// Single fused kernel, one 512-thread block per 32 consecutive output rows of
// a batch. Each block independently:
//   1) loads the batch's S=1024 durations (int2/thread; L2-resident),
//   2) warp-shuffle scans them into an inclusive cum[] in shared memory,
//   3) 32 lanes binary-search cum for their row's source index + write mask,
//   4) 4 groups of 128 lanes copy 8 rows each: 8 independent float4 loads
//      (MLP=8) then 8 streaming stores.
// No inter-block communication of any kind.
// ---------------------------------------------------------------------------
__global__ void __launch_bounds__(512, 4)
lenreg_kernel(const float* __restrict__ x,
              const int*   __restrict__ dur,
              float* __restrict__ out,
              float* __restrict__ mask,
              int S, int T, int D)
{
    __shared__ int cum[MAX_S];
    __shared__ int wsum[16];
    __shared__ int idx_sh[RPB];

    const int cpb = T / RPB;                     // chunks per batch (=64)
    const int b   = blockIdx.x / cpb;
    const int t0c = (blockIdx.x - b * cpb) * RPB;   // first row (in-batch)
    const int tid = threadIdx.x;
    const int ln  = tid & 31;
    const int wid = tid >> 5;                    // 16 warps

    // ---- 1) load 2 durations per thread -----------------------------------
    const int2 d2 = *reinterpret_cast<const int2*>(dur + b * S + tid * 2);
    const int s = d2.x + d2.y;

    // ---- 2) block-wide inclusive scan -------------------------------------
    int v = s;                                   // intra-warp inclusive scan
    #pragma unroll
    for (int o = 1; o < 32; o <<= 1) {
        int n = __shfl_up_sync(0xffffffffu, v, o);
        if (ln >= o) v += n;
    }
    if (ln == 31) wsum[wid] = v;
    __syncthreads();
    if (tid < 16) {                              // scan the 16 warp totals
        int w = wsum[tid];
        #pragma unroll
        for (int o = 1; o < 16; o <<= 1) {
            int n = __shfl_up_sync(0xffffu, w, o);
            if (tid >= o) w += n;
        }
        wsum[tid] = w;
    }
    __syncthreads();

    const int base = (wid ? wsum[wid - 1] : 0) + (v - s);  // exclusive prefix
    const int len  = wsum[15];

    int2 c;                                      // inclusive cum of 2 elems
    c.x = base + d2.x;
    c.y = c.x + d2.y;
    *reinterpret_cast<int2*>(cum + tid * 2) = c; // STS.64, conflict-free
    __syncthreads();

    // ---- 3) 32 parallel binary searches + mask ----------------------------
    if (tid < RPB) {
        const int t = t0c + tid;
        // searchsorted(cum, t, side='right'): count of cum[j] <= t
        int lo = 0, hi = S;
        while (lo < hi) {
            const int mid  = (lo + hi) >> 1;
            const bool le  = (cum[mid] <= t);
            lo = le ? mid + 1 : lo;
            hi = le ? hi : mid;
        }
        idx_sh[tid] = min(lo, S - 1);
        mask[b * T + t] = (t >= len) ? 1.0f : 0.0f;
    }
    __syncthreads();

    // ---- 4) copy: 4 groups x 8 rows ---------------------------------------
    const int lane = tid & 127;
    const int grp  = tid >> 7;                   // 0..3
    const int t0   = t0c + grp * ROWS;
    const int row0 = b * T + t0;                 // global output row

    int idx[ROWS];
    #pragma unroll
    for (int r = 0; r < ROWS; ++r)
        idx[r] = idx_sh[grp * ROWS + r];         // LDS broadcast

    const float4* __restrict__ xv =
        reinterpret_cast<const float4*>(x + (size_t)b * S * D) + lane;
    float4* __restrict__ dst =
        reinterpret_cast<float4*>(out + (size_t)row0 * D) + lane;
    const int strideV = D >> 2;                  // float4s per row (=128)

    float4 vv[ROWS];                             // 8 independent loads (MLP=8)
    #pragma unroll
    for (int r = 0; r < ROWS; ++r) {
        if (t0 + r < len)
            vv[r] = xv[(size_t)idx[r] * strideV];
        else
            vv[r] = make_float4(0.f, 0.f, 0.f, 0.f);
    }
    #pragma unroll
    for (int r = 0; r < ROWS; ++r)
        __stcs(dst + (size_t)r * strideV, vv[r]);
}

// ---------------------------------------------------------------------------
extern "C" void kernel_launch(void* const* d_in, const int* in_sizes, int n_in,
                              void* d_out, int out_size) {
    const float* x   = (const float*)d_in[0];
    const int*   dur = (const int*)d_in[1];

    const int BS = in_sizes[1];               // B*S = 65536
    const int B  = BATCH;                     // 64
    const int S  = BS / B;                    // 1024
    const int D  = in_sizes[0] / BS;          // 512
    const int T  = out_size / (B * (D + 1));  // 2048

    float* out  = (float*)d_out;
    float* mask = out + (size_t)B * T * D;

    lenreg_kernel<<<(B * T) / RPB, 512>>>(x, dur, out, mask, S, T, D);
}